// round 1
// baseline (speedup 1.0000x reference)
#include <cuda_runtime.h>

#define DD 64
#define RR 16
#define NN 50000
#define BLK_M 128

typedef unsigned long long ull;

// Static scratch (allocation-free rule): relation-transformed features + layer-1 output
__device__ float g_H[(size_t)RR * NN * DD];   // ~204.8 MB
__device__ float g_x1[(size_t)NN * DD];       // ~12.8 MB

__device__ __forceinline__ ull dup2(float x) {
    ull r; asm("mov.b64 %0, {%1, %1};" : "=l"(r) : "f"(x)); return r;
}
__device__ __forceinline__ ull fma2(ull a, ull b, ull c) {
    ull d; asm("fma.rn.f32x2 %0, %1, %2, %3;" : "=l"(d) : "l"(a), "l"(b), "l"(c)); return d;
}
__device__ __forceinline__ float lo2(ull v) { return __uint_as_float((unsigned)(v & 0xffffffffULL)); }
__device__ __forceinline__ float hi2(ull v) { return __uint_as_float((unsigned)(v >> 32)); }

// H[r][n][o] = sum_i x[n][i] * W[r][i][o]
// Tile: 128 nodes x 64 outputs, K=64 full. 128 threads, each 8x8 micro-tile.
// L2 variant reads g_x1 and applies relu(x + bias) on load (fuses layer-1 epilogue).
template<bool L2>
__global__ void __launch_bounds__(128, 2) transform_kernel(
    const float* __restrict__ x_in, const float* __restrict__ W,
    const float* __restrict__ bias, int N)
{
    __shared__ float Xs[BLK_M][DD];   // 32 KB, XOR-swizzled columns
    __shared__ float Ws[DD][DD];      // 16 KB  (total = 48 KB static, at the limit)

    const float* __restrict__ x = L2 ? (const float*)g_x1 : x_in;

    const int r  = blockIdx.y;
    const int n0 = blockIdx.x * BLK_M;
    const int tid = threadIdx.x;

    // Load W_r (row-major [i][o]) straight into smem
    const float* Wr = W + (size_t)r * DD * DD;
    #pragma unroll
    for (int it = 0; it < 8; ++it) {
        int f = it * 128 + tid;                       // 1024 float4s
        reinterpret_cast<float4*>(&Ws[0][0])[f] =
            reinterpret_cast<const float4*>(Wr)[f];
    }

    // Load x tile with XOR swizzle: logical col c stored at (c ^ (row & 24))
    #pragma unroll
    for (int it = 0; it < 16; ++it) {
        int f   = it * 128 + tid;                     // 2048 float4s
        int row = f >> 4;
        int c16 = f & 15;
        int c4  = c16 << 2;
        int n   = n0 + row;
        float4 v = make_float4(0.f, 0.f, 0.f, 0.f);
        if (n < N) v = reinterpret_cast<const float4*>(x)[(size_t)n * 16 + c16];
        if (L2) {
            v.x = fmaxf(v.x + bias[c4 + 0], 0.f);
            v.y = fmaxf(v.y + bias[c4 + 1], 0.f);
            v.z = fmaxf(v.z + bias[c4 + 2], 0.f);
            v.w = fmaxf(v.w + bias[c4 + 3], 0.f);
        }
        int sw = row & 24;
        Xs[row][(c4 + 0) ^ sw] = v.x;
        Xs[row][(c4 + 1) ^ sw] = v.y;
        Xs[row][(c4 + 2) ^ sw] = v.z;
        Xs[row][(c4 + 3) ^ sw] = v.w;
    }
    __syncthreads();

    const int rg = tid >> 3;       // 0..15
    const int cg = tid & 7;        // 0..7
    const int r0 = rg << 3;        // node rows r0..r0+7
    const int c0 = cg << 3;        // output cols c0..c0+7
    const int sw = r0 & 24;        // constant swizzle for all 8 rows of this thread

    // acc[i][c] = f32x2 pair {out[r0+i][c0+2c], out[r0+i][c0+2c+1]}
    ull acc[8][4];
    #pragma unroll
    for (int i = 0; i < 8; ++i)
        #pragma unroll
        for (int c = 0; c < 4; ++c) acc[i][c] = 0ULL;

    #pragma unroll 8
    for (int k = 0; k < DD; ++k) {
        ull ad[8];
        #pragma unroll
        for (int i = 0; i < 8; ++i) ad[i] = dup2(Xs[r0 + i][k ^ sw]);
        // b pairs loaded directly as 8-byte f32x2 from Ws[k]
        const ull* wr = reinterpret_cast<const ull*>(&Ws[k][0]);
        ull b2[4];
        #pragma unroll
        for (int c = 0; c < 4; ++c) b2[c] = wr[cg * 4 + c];
        #pragma unroll
        for (int i = 0; i < 8; ++i)
            #pragma unroll
            for (int c = 0; c < 4; ++c)
                acc[i][c] = fma2(ad[i], b2[c], acc[i][c]);
    }

    // Store H rows (f32x2 pairs are already column-adjacent)
    #pragma unroll
    for (int i = 0; i < 8; ++i) {
        int n = n0 + r0 + i;
        if (n < N) {
            float4 v0 = make_float4(lo2(acc[i][0]), hi2(acc[i][0]),
                                    lo2(acc[i][1]), hi2(acc[i][1]));
            float4 v1 = make_float4(lo2(acc[i][2]), hi2(acc[i][2]),
                                    lo2(acc[i][3]), hi2(acc[i][3]));
            float* p = &g_H[((size_t)r * N + n) * DD + c0];
            *reinterpret_cast<float4*>(p)     = v0;
            *reinterpret_cast<float4*>(p + 4) = v1;
        }
    }
}

// Per edge e: out[dst] += H[rel][src] / max(pl, eps).
// 16 threads per edge, float4 chunks, vectorized L2-resident reductions.
__global__ void __launch_bounds__(256) scatter_kernel(
    const int* __restrict__ src, const int* __restrict__ dst,
    const int* __restrict__ et,  const float* __restrict__ pl,
    float* __restrict__ out_p, int toG, int E0, int nTot, int N)
{
    __shared__ int   s_s[16], s_d[16], s_r[16];
    __shared__ float s_w[16];
    float* __restrict__ out = toG ? (float*)g_x1 : out_p;

    const int tid   = threadIdx.x;
    const int ebase = blockIdx.x * 16;
    if (tid < 16) {
        int e = ebase + tid;
        if (e < nTot) {
            int s, d;
            if (e < E0) { s = src[e]; d = dst[e]; }
            else        { s = e - E0; d = s; }       // self loop
            s_s[tid] = s;
            s_d[tid] = d;
            s_r[tid] = et[e];
            s_w[tid] = 1.0f / fmaxf(pl[e], 1e-9f);
        }
    }
    __syncthreads();

    const int el = tid >> 4;
    const int ch = tid & 15;
    const int e  = ebase + el;
    if (e >= nTot) return;

    const float4 v = *reinterpret_cast<const float4*>(
        &g_H[((size_t)s_r[el] * N + s_s[el]) * DD + (ch << 2)]);
    const float w  = s_w[el];
    float a = v.x * w, b = v.y * w, c = v.z * w, d = v.w * w;
    float* p = &out[(size_t)s_d[el] * DD + (ch << 2)];
    asm volatile("red.global.add.v4.f32 [%0], {%1, %2, %3, %4};"
                 :: "l"(p), "f"(a), "f"(b), "f"(c), "f"(d) : "memory");
}

__global__ void zero_x1_kernel(int n4)
{
    int i = blockIdx.x * blockDim.x + threadIdx.x;
    if (i < n4) reinterpret_cast<float4*>(g_x1)[i] = make_float4(0.f, 0.f, 0.f, 0.f);
}

__global__ void relu_bias_kernel(float* __restrict__ out,
                                 const float* __restrict__ bias, int n4)
{
    int f = blockIdx.x * blockDim.x + threadIdx.x;
    if (f >= n4) return;
    int c4 = (f & 15) << 2;
    float4 v = reinterpret_cast<float4*>(out)[f];
    v.x = fmaxf(v.x + bias[c4 + 0], 0.f);
    v.y = fmaxf(v.y + bias[c4 + 1], 0.f);
    v.z = fmaxf(v.z + bias[c4 + 2], 0.f);
    v.w = fmaxf(v.w + bias[c4 + 3], 0.f);
    reinterpret_cast<float4*>(out)[f] = v;
}

extern "C" void kernel_launch(void* const* d_in, const int* in_sizes, int n_in,
                              void* d_out, int out_size)
{
    const float* x   = (const float*)d_in[0];
    const int*   ei  = (const int*)  d_in[1];   // [2, E]: row0 = src, row1 = dst
    const int*   et  = (const int*)  d_in[2];   // [E + N]
    const float* pl  = (const float*)d_in[3];   // [E + N]
    const float* w1  = (const float*)d_in[4];   // [R, D, D]
    const float* b1  = (const float*)d_in[5];
    const float* w2  = (const float*)d_in[6];
    const float* b2  = (const float*)d_in[7];

    const int N    = in_sizes[0] / DD;
    const int E0   = in_sizes[1] / 2;
    const int nTot = in_sizes[2];               // E + N (self loops)
    const int R    = in_sizes[4] / (DD * DD);

    const dim3 tgrid((N + BLK_M - 1) / BLK_M, R);
    const int  sgrid = (nTot + 15) / 16;
    const int  n4    = N * (DD / 4);

    // ---- layer 1 ----
    transform_kernel<false><<<tgrid, 128>>>(x, w1, nullptr, N);
    zero_x1_kernel<<<(n4 + 255) / 256, 256>>>(n4);
    scatter_kernel<<<sgrid, 256>>>(ei, ei + E0, et, pl, nullptr, 1, E0, nTot, N);

    // ---- layer 2 (relu(x1 + b1) fused into transform load) ----
    transform_kernel<true><<<tgrid, 128>>>(nullptr, w2, b1, N);
    cudaMemsetAsync(d_out, 0, (size_t)N * DD * sizeof(float));
    scatter_kernel<<<sgrid, 256>>>(ei, ei + E0, et, pl, (float*)d_out, 0, E0, nTot, N);
    relu_bias_kernel<<<(n4 + 255) / 256, 256>>>((float*)d_out, b2, n4);
}

// round 3
// speedup vs baseline: 1.4462x; 1.4462x over previous
#include <cuda_runtime.h>
#include <cuda_bf16.h>
#include <cstdint>

#define DD 64
#define RR 16
#define BLK_M 128

typedef unsigned long long ull;

// Static scratch (allocation-free rule)
__device__ float g_H[(size_t)RR * 50048 * DD];            // relation-transformed features
__device__ float g_x1[(size_t)50048 * DD];                // layer-1 output
__device__ __nv_bfloat16 g_Wt[2][RR][2][DD][DD];          // [layer][r][hi/lo][o][k]

__device__ __forceinline__ uint32_t smem_u32(const void* p) {
    uint32_t a;
    asm("{ .reg .u64 t; cvta.to.shared.u64 t, %1; cvt.u32.u64 %0, t; }" : "=r"(a) : "l"(p));
    return a;
}

__device__ __forceinline__ void ldsm_x4(uint32_t* r, uint32_t addr) {
    asm volatile("ldmatrix.sync.aligned.m8n8.x4.shared.b16 {%0,%1,%2,%3}, [%4];"
                 : "=r"(r[0]), "=r"(r[1]), "=r"(r[2]), "=r"(r[3]) : "r"(addr));
}

__device__ __forceinline__ void mma_bf16(float* c, const uint32_t* a, const uint32_t* b) {
    asm volatile(
        "mma.sync.aligned.m16n8k16.row.col.f32.bf16.bf16.f32 "
        "{%0,%1,%2,%3}, {%4,%5,%6,%7}, {%8,%9}, {%0,%1,%2,%3};"
        : "+f"(c[0]), "+f"(c[1]), "+f"(c[2]), "+f"(c[3])
        : "r"(a[0]), "r"(a[1]), "r"(a[2]), "r"(a[3]), "r"(b[0]), "r"(b[1]));
}

// ---------------- W pre-convert: fp32 [r][i][o] -> bf16 hi/lo, transposed [o][k=i] ----------------
__global__ void convert_W(const float* __restrict__ W1, const float* __restrict__ W2)
{
    const int lr = blockIdx.x;               // 0..31
    const int layer = lr >> 4, r = lr & 15;
    const float* Wr = (layer ? W2 : W1) + (size_t)r * DD * DD;
    __shared__ float tile[DD][DD + 1];
    const int tid = threadIdx.x;             // 256
    #pragma unroll
    for (int it = 0; it < 16; ++it) {
        int idx = it * 256 + tid;
        tile[idx >> 6][idx & 63] = Wr[idx];  // tile[i][o]
    }
    __syncthreads();
    #pragma unroll
    for (int it = 0; it < 16; ++it) {
        int idx = it * 256 + tid;
        int o = idx >> 6, k = idx & 63;
        float w = tile[k][o];
        __nv_bfloat16 h = __float2bfloat16_rn(w);
        __nv_bfloat16 l = __float2bfloat16_rn(w - __bfloat162float(h));
        g_Wt[layer][r][0][o][k] = h;
        g_Wt[layer][r][1][o][k] = l;
    }
}

// ---------------- HMMA transform ----------------
// H[r][n][o] = sum_i x[n][i] * W[r][i][o], 3-term bf16 hi/lo split, fp32 accum.
// CTA = 128-node tile, loops all R relations. 4 warps, each 32 rows (2 m16 tiles).

#define WPITCH 144                 // padded bytes per Wt smem row (72 bf16) -> conflict-free B frags
#define OFF_XHI 0
#define OFF_XLO 16384
#define OFF_W   32768              // 2 slots x (hi 9216 + lo 9216)
#define WSLOT   18432
#define SMEM_BYTES (32768 + 2 * WSLOT)

template<bool L2>
__global__ void __launch_bounds__(128, 2) transform_mma(
    const float* __restrict__ x_in, const float* __restrict__ bias, int N)
{
    extern __shared__ char sb[];
    const uint32_t sbase = smem_u32(sb);

    const float* __restrict__ x = L2 ? (const float*)g_x1 : x_in;
    const int tid  = threadIdx.x;
    const int wid  = tid >> 5;
    const int lane = tid & 31;
    const int n0   = blockIdx.x * BLK_M;

    // ---- X tile: fp32 -> bf16 hi/lo, LDSM-swizzled smem (chunk c16 ^ (row&7)) ----
    #pragma unroll
    for (int it = 0; it < 8; ++it) {
        int f   = it * 128 + tid;            // 1024 16B-chunks
        int row = f >> 3;
        int c8  = f & 7;                     // 8-float chunk
        int n   = n0 + row;
        float4 v0 = make_float4(0.f,0.f,0.f,0.f), v1 = v0;
        if (n < N) {
            v0 = reinterpret_cast<const float4*>(x)[(size_t)n * 16 + c8 * 2];
            v1 = reinterpret_cast<const float4*>(x)[(size_t)n * 16 + c8 * 2 + 1];
        }
        if (L2) {
            int c = c8 * 8;
            v0.x = fmaxf(v0.x + bias[c+0], 0.f); v0.y = fmaxf(v0.y + bias[c+1], 0.f);
            v0.z = fmaxf(v0.z + bias[c+2], 0.f); v0.w = fmaxf(v0.w + bias[c+3], 0.f);
            v1.x = fmaxf(v1.x + bias[c+4], 0.f); v1.y = fmaxf(v1.y + bias[c+5], 0.f);
            v1.z = fmaxf(v1.z + bias[c+6], 0.f); v1.w = fmaxf(v1.w + bias[c+7], 0.f);
        }
        float vf[8] = {v0.x, v0.y, v0.z, v0.w, v1.x, v1.y, v1.z, v1.w};
        uint32_t hi[4], lo[4];
        #pragma unroll
        for (int j = 0; j < 4; ++j) {
            __nv_bfloat16 h0 = __float2bfloat16_rn(vf[2*j]);
            __nv_bfloat16 h1 = __float2bfloat16_rn(vf[2*j+1]);
            __nv_bfloat16 l0 = __float2bfloat16_rn(vf[2*j]   - __bfloat162float(h0));
            __nv_bfloat16 l1 = __float2bfloat16_rn(vf[2*j+1] - __bfloat162float(h1));
            hi[j] = ((uint32_t)__bfloat16_as_ushort(h1) << 16) | __bfloat16_as_ushort(h0);
            lo[j] = ((uint32_t)__bfloat16_as_ushort(l1) << 16) | __bfloat16_as_ushort(l0);
        }
        uint32_t off = (uint32_t)(row * 128 + ((c8 ^ (row & 7)) << 4));
        *reinterpret_cast<uint4*>(sb + OFF_XHI + off) = make_uint4(hi[0],hi[1],hi[2],hi[3]);
        *reinterpret_cast<uint4*>(sb + OFF_XLO + off) = make_uint4(lo[0],lo[1],lo[2],lo[3]);
    }

    // ---- W stage: copy pre-converted bf16 hi/lo into padded smem slot ----
    auto load_W = [&](int r, int s) {
        const uint4* src = reinterpret_cast<const uint4*>(&g_Wt[L2 ? 1 : 0][r][0][0][0]);
        char* dst = sb + OFF_W + s * WSLOT;
        #pragma unroll
        for (int it = 0; it < 8; ++it) {
            int idx  = it * 128 + tid;       // 1024 uint4 (hi 512, lo 512)
            int half = idx >> 9;
            int rem  = idx & 511;
            int o    = rem >> 3;
            int j    = rem & 7;
            *reinterpret_cast<uint4*>(dst + half * 9216 + o * WPITCH + j * 16) = src[idx];
        }
    };

    load_W(0, 0);
    __syncthreads();

    const uint32_t xhi_base = sbase + OFF_XHI;
    const uint32_t xlo_base = sbase + OFF_XLO;

    for (int r = 0; r < RR; ++r) {
        const int s = r & 1;
        if (r + 1 < RR) load_W(r + 1, s ^ 1);

        const char* wh = sb + OFF_W + s * WSLOT;
        const char* wl = wh + 9216;

        float acc[2][8][4];
        #pragma unroll
        for (int mt = 0; mt < 2; ++mt)
            #pragma unroll
            for (int t = 0; t < 8; ++t)
                #pragma unroll
                for (int j = 0; j < 4; ++j) acc[mt][t][j] = 0.f;

        #pragma unroll
        for (int ks = 0; ks < 4; ++ks) {
            // A fragments (hi, lo) for 2 m16 tiles
            uint32_t ahi[2][4], alo[2][4];
            #pragma unroll
            for (int mt = 0; mt < 2; ++mt) {
                int row = wid * 32 + mt * 16 + (lane & 15);
                int c16 = ks * 2 + (lane >> 4);
                uint32_t off = (uint32_t)(row * 128 + ((c16 ^ (row & 7)) << 4));
                ldsm_x4(ahi[mt], xhi_base + off);
                ldsm_x4(alo[mt], xlo_base + off);
            }
            // B fragments: one LDS.32 per reg, conflict-free via 144B pitch
            const int nb = (lane >> 2);
            const int kb = 2 * (lane & 3) + ks * 16;
            uint32_t bh[8][2], bl[8][2];
            #pragma unroll
            for (int t = 0; t < 8; ++t) {
                int o = nb + 8 * t;
                bh[t][0] = *reinterpret_cast<const uint32_t*>(wh + o * WPITCH + kb * 2);
                bh[t][1] = *reinterpret_cast<const uint32_t*>(wh + o * WPITCH + (kb + 8) * 2);
                bl[t][0] = *reinterpret_cast<const uint32_t*>(wl + o * WPITCH + kb * 2);
                bl[t][1] = *reinterpret_cast<const uint32_t*>(wl + o * WPITCH + (kb + 8) * 2);
            }
            #pragma unroll
            for (int mt = 0; mt < 2; ++mt)
                #pragma unroll
                for (int t = 0; t < 8; ++t) {
                    mma_bf16(acc[mt][t], ahi[mt], bh[t]);
                    mma_bf16(acc[mt][t], alo[mt], bh[t]);
                    mma_bf16(acc[mt][t], ahi[mt], bl[t]);
                }
        }

        // Epilogue: c0,c1 -> row g; c2,c3 -> row g+8 (cols 2(lane&3)+{0,1} of n8 tile)
        #pragma unroll
        for (int mt = 0; mt < 2; ++mt) {
            int nA = n0 + wid * 32 + mt * 16 + (lane >> 2);
            int nB = nA + 8;
            #pragma unroll
            for (int t = 0; t < 8; ++t) {
                int col = t * 8 + 2 * (lane & 3);
                if (nA < N)
                    *reinterpret_cast<float2*>(&g_H[((size_t)r * N + nA) * DD + col]) =
                        make_float2(acc[mt][t][0], acc[mt][t][1]);
                if (nB < N)
                    *reinterpret_cast<float2*>(&g_H[((size_t)r * N + nB) * DD + col]) =
                        make_float2(acc[mt][t][2], acc[mt][t][3]);
            }
        }
        __syncthreads();
    }
}

// ---------------- scatter + aux (proven in R1) ----------------

__global__ void __launch_bounds__(256) scatter_kernel(
    const int* __restrict__ src, const int* __restrict__ dst,
    const int* __restrict__ et,  const float* __restrict__ pl,
    float* __restrict__ out_p, int toG, int E0, int nTot, int N)
{
    __shared__ int   s_s[16], s_d[16], s_r[16];
    __shared__ float s_w[16];
    float* __restrict__ out = toG ? (float*)g_x1 : out_p;

    const int tid   = threadIdx.x;
    const int ebase = blockIdx.x * 16;
    if (tid < 16) {
        int e = ebase + tid;
        if (e < nTot) {
            int s, d;
            if (e < E0) { s = src[e]; d = dst[e]; }
            else        { s = e - E0; d = s; }
            s_s[tid] = s; s_d[tid] = d; s_r[tid] = et[e];
            s_w[tid] = 1.0f / fmaxf(pl[e], 1e-9f);
        }
    }
    __syncthreads();

    const int el = tid >> 4;
    const int ch = tid & 15;
    const int e  = ebase + el;
    if (e >= nTot) return;

    const float4 v = *reinterpret_cast<const float4*>(
        &g_H[((size_t)s_r[el] * N + s_s[el]) * DD + (ch << 2)]);
    const float w  = s_w[el];
    float a = v.x * w, b = v.y * w, c = v.z * w, d = v.w * w;
    float* p = &out[(size_t)s_d[el] * DD + (ch << 2)];
    asm volatile("red.global.add.v4.f32 [%0], {%1, %2, %3, %4};"
                 :: "l"(p), "f"(a), "f"(b), "f"(c), "f"(d) : "memory");
}

__global__ void zero_x1_kernel(int n4)
{
    int i = blockIdx.x * blockDim.x + threadIdx.x;
    if (i < n4) reinterpret_cast<float4*>(g_x1)[i] = make_float4(0.f, 0.f, 0.f, 0.f);
}

__global__ void relu_bias_kernel(float* __restrict__ out,
                                 const float* __restrict__ bias, int n4)
{
    int f = blockIdx.x * blockDim.x + threadIdx.x;
    if (f >= n4) return;
    int c4 = (f & 15) << 2;
    float4 v = reinterpret_cast<float4*>(out)[f];
    v.x = fmaxf(v.x + bias[c4 + 0], 0.f);
    v.y = fmaxf(v.y + bias[c4 + 1], 0.f);
    v.z = fmaxf(v.z + bias[c4 + 2], 0.f);
    v.w = fmaxf(v.w + bias[c4 + 3], 0.f);
    reinterpret_cast<float4*>(out)[f] = v;
}

extern "C" void kernel_launch(void* const* d_in, const int* in_sizes, int n_in,
                              void* d_out, int out_size)
{
    const float* x   = (const float*)d_in[0];
    const int*   ei  = (const int*)  d_in[1];
    const int*   et  = (const int*)  d_in[2];
    const float* pl  = (const float*)d_in[3];
    const float* w1  = (const float*)d_in[4];
    const float* b1  = (const float*)d_in[5];
    const float* w2  = (const float*)d_in[6];
    const float* b2  = (const float*)d_in[7];

    const int N    = in_sizes[0] / DD;
    const int E0   = in_sizes[1] / 2;
    const int nTot = in_sizes[2];

    const int tgrid = (N + BLK_M - 1) / BLK_M;
    const int sgrid = (nTot + 15) / 16;
    const int n4    = N * (DD / 4);

    cudaFuncSetAttribute(transform_mma<false>,
                         cudaFuncAttributeMaxDynamicSharedMemorySize, SMEM_BYTES);
    cudaFuncSetAttribute(transform_mma<true>,
                         cudaFuncAttributeMaxDynamicSharedMemorySize, SMEM_BYTES);

    convert_W<<<32, 256>>>(w1, w2);

    // ---- layer 1 ----
    transform_mma<false><<<tgrid, 128, SMEM_BYTES>>>(x, nullptr, N);
    zero_x1_kernel<<<(n4 + 255) / 256, 256>>>(n4);
    scatter_kernel<<<sgrid, 256>>>(ei, ei + E0, et, pl, nullptr, 1, E0, nTot, N);

    // ---- layer 2 (relu(x1 + b1) fused into transform load) ----
    transform_mma<true><<<tgrid, 128, SMEM_BYTES>>>(nullptr, b1, N);
    cudaMemsetAsync(d_out, 0, (size_t)N * DD * sizeof(float));
    scatter_kernel<<<sgrid, 256>>>(ei, ei + E0, et, pl, (float*)d_out, 0, E0, nTot, N);
    relu_bias_kernel<<<(n4 + 255) / 256, 256>>>((float*)d_out, b2, n4);
}

// round 4
// speedup vs baseline: 1.7088x; 1.1816x over previous
#include <cuda_runtime.h>
#include <cuda_bf16.h>
#include <cstdint>

#define DD 64
#define RR 16
#define MAXE 851968
#define TILE_M 128

typedef unsigned int u32;

// ---- static scratch (allocation-free rule) ----
__device__ float g_x1[(size_t)50048 * DD];                // layer-1 output (12.8MB, L2-resident)
__device__ __nv_bfloat16 g_Wt[2][RR][2][DD][DD];          // [layer][r][hi/lo][o][k]
__device__ int   g_src[MAXE];
__device__ int   g_dstA[MAXE];
__device__ float g_wgt[MAXE];
__device__ u32   g_rcnt[RR];
__device__ u32   g_roff[RR + 1];
__device__ u32   g_pos[RR];
__device__ u32   g_tiles[8192];
__device__ u32   g_ntiles;

__device__ __forceinline__ uint32_t smem_u32(const void* p) {
    uint32_t a;
    asm("{ .reg .u64 t; cvta.to.shared.u64 t, %1; cvt.u32.u64 %0, t; }" : "=r"(a) : "l"(p));
    return a;
}

__device__ __forceinline__ void ldsm_x4(uint32_t* r, uint32_t addr) {
    asm volatile("ldmatrix.sync.aligned.m8n8.x4.shared.b16 {%0,%1,%2,%3}, [%4];"
                 : "=r"(r[0]), "=r"(r[1]), "=r"(r[2]), "=r"(r[3]) : "r"(addr));
}

__device__ __forceinline__ void mma_bf16(float* c, const uint32_t* a, const uint32_t* b) {
    asm volatile(
        "mma.sync.aligned.m16n8k16.row.col.f32.bf16.bf16.f32 "
        "{%0,%1,%2,%3}, {%4,%5,%6,%7}, {%8,%9}, {%0,%1,%2,%3};"
        : "+f"(c[0]), "+f"(c[1]), "+f"(c[2]), "+f"(c[3])
        : "r"(a[0]), "r"(a[1]), "r"(a[2]), "r"(a[3]), "r"(b[0]), "r"(b[1]));
}

// ---------------- W pre-convert: fp32 [r][i][o] -> bf16 hi/lo, transposed [o][k=i] ----------------
__global__ void convert_W(const float* __restrict__ W1, const float* __restrict__ W2)
{
    const int lr = blockIdx.x;               // 0..31
    const int layer = lr >> 4, r = lr & 15;
    const float* Wr = (layer ? W2 : W1) + (size_t)r * DD * DD;
    __shared__ float tile[DD][DD + 1];
    const int tid = threadIdx.x;             // 256
    #pragma unroll
    for (int it = 0; it < 16; ++it) {
        int idx = it * 256 + tid;
        tile[idx >> 6][idx & 63] = Wr[idx];  // tile[i][o]
    }
    __syncthreads();
    #pragma unroll
    for (int it = 0; it < 16; ++it) {
        int idx = it * 256 + tid;
        int o = idx >> 6, k = idx & 63;
        float w = tile[k][o];
        __nv_bfloat16 h = __float2bfloat16_rn(w);
        __nv_bfloat16 l = __float2bfloat16_rn(w - __bfloat162float(h));
        g_Wt[layer][r][0][o][k] = h;
        g_Wt[layer][r][1][o][k] = l;
    }
}

// ---------------- counting sort by relation ----------------

__global__ void init_cnt()
{
    if (threadIdx.x < RR) g_rcnt[threadIdx.x] = 0;
}

__global__ void hist_kernel(const int* __restrict__ et, int nTot)
{
    __shared__ u32 h[RR];
    const int tid = threadIdx.x;
    if (tid < RR) h[tid] = 0;
    __syncthreads();
    const int base = blockIdx.x * 2048;
    #pragma unroll
    for (int j = 0; j < 8; ++j) {
        int e = base + j * 256 + tid;
        if (e < nTot) atomicAdd(&h[et[e] & 15], 1u);
    }
    __syncthreads();
    if (tid < RR && h[tid]) atomicAdd(&g_rcnt[tid], h[tid]);
}

__global__ void scan_tiles()
{
    const int lane = threadIdx.x;
    u32 c = (lane < RR) ? g_rcnt[lane] : 0;
    u32 x = c;
    #pragma unroll
    for (int s = 1; s < 16; s <<= 1) {
        u32 y = __shfl_up_sync(0xFFFFFFFFu, x, s);
        if (lane >= s) x += y;
    }
    u32 off = x - c;
    if (lane < RR) { g_roff[lane] = off; g_pos[lane] = off; }
    if (lane == RR - 1) g_roff[RR] = x;

    u32 nt = (c + TILE_M - 1) / TILE_M;
    u32 tx = nt;
    #pragma unroll
    for (int s = 1; s < 16; s <<= 1) {
        u32 y = __shfl_up_sync(0xFFFFFFFFu, tx, s);
        if (lane >= s) tx += y;
    }
    u32 tb = tx - nt;
    if (lane < RR)
        for (u32 t = 0; t < nt; ++t)
            g_tiles[tb + t] = (off + t * TILE_M) | ((u32)lane << 24);
    if (lane == RR - 1) g_ntiles = tx;
}

__global__ void fill_kernel(const int* __restrict__ ei, const int* __restrict__ et,
                            const float* __restrict__ pl, int E0, int nTot)
{
    __shared__ u32 h[RR];
    __shared__ u32 base16[RR];
    const int tid = threadIdx.x;
    if (tid < RR) h[tid] = 0;
    __syncthreads();
    const int b = blockIdx.x * 2048;
    int rel[8]; u32 rank[8];
    #pragma unroll
    for (int j = 0; j < 8; ++j) {
        int e = b + j * 256 + tid;
        rel[j] = -1;
        if (e < nTot) { rel[j] = et[e] & 15; rank[j] = atomicAdd(&h[rel[j]], 1u); }
    }
    __syncthreads();
    if (tid < RR) base16[tid] = h[tid] ? atomicAdd(&g_pos[tid], h[tid]) : 0u;
    __syncthreads();
    #pragma unroll
    for (int j = 0; j < 8; ++j) {
        if (rel[j] >= 0) {
            int e = b + j * 256 + tid;
            u32 p = base16[rel[j]] + rank[j];
            int s, d;
            if (e < E0) { s = ei[e]; d = ei[E0 + e]; }
            else        { s = e - E0; d = s; }
            g_src[p]  = s;
            g_dstA[p] = d;
            g_wgt[p]  = 1.0f / fmaxf(pl[e], 1e-9f);
        }
    }
}

// ---------------- fused edge GEMM + scatter ----------------
// One CTA = 128 same-relation edges: gather (x[src]*w) -> bf16 hi/lo smem,
// 3-term HMMA vs W_r, epilogue red.global.add.v4 into out[dst].

#define WPITCH 144
#define OFF_XHI 0
#define OFF_XLO 16384
#define OFF_W   32768
#define OFF_SRC 51200
#define OFF_DST 51712
#define OFF_WG  52224
#define SMEM_BYTES 52736

template<bool L2>
__global__ void __launch_bounds__(128, 3) edge_mma(
    const float* __restrict__ x_in, const float* __restrict__ bias,
    float* __restrict__ out_p, int toG, int N)
{
    const u32 bid = blockIdx.x;
    if (bid >= g_ntiles) return;

    extern __shared__ char sb[];
    const uint32_t sbase = smem_u32(sb);

    const u32 tdesc = g_tiles[bid];
    const int start = (int)(tdesc & 0xFFFFFF);
    const int rel   = (int)(tdesc >> 24);
    const int cnt   = min(TILE_M, (int)g_roff[rel + 1] - start);

    const float* __restrict__ x = L2 ? (const float*)g_x1 : x_in;
    float* __restrict__ out = toG ? (float*)g_x1 : out_p;

    const int tid  = threadIdx.x;
    const int wid  = tid >> 5;
    const int lane = tid & 31;

    // stage edge meta (invalid rows -> src 0, w 0: row becomes zeros, no OOB)
    if (tid < TILE_M) {
        int s = 0, d = 0; float w = 0.f;
        if (tid < cnt) { s = g_src[start + tid]; d = g_dstA[start + tid]; w = g_wgt[start + tid]; }
        ((int*)(sb + OFF_SRC))[tid] = s;
        ((int*)(sb + OFF_DST))[tid] = d;
        ((float*)(sb + OFF_WG))[tid] = w;
    }

    // stage W_r (bf16 hi/lo, padded rows)
    {
        const uint4* src = reinterpret_cast<const uint4*>(&g_Wt[L2 ? 1 : 0][rel][0][0][0]);
        #pragma unroll
        for (int it = 0; it < 8; ++it) {
            int idx  = it * 128 + tid;       // 1024 uint4 (hi 512, lo 512)
            int half = idx >> 9;
            int rem  = idx & 511;
            int o    = rem >> 3;
            int j    = rem & 7;
            *reinterpret_cast<uint4*>(sb + OFF_W + half * 9216 + o * WPITCH + j * 16) = src[idx];
        }
    }
    __syncthreads();

    // gather x rows, scale by w, split bf16 hi/lo into LDSM-swizzled smem
    #pragma unroll
    for (int p = 0; p < 16; ++p) {
        int row = p * 8 + (tid >> 4);
        int c4  = tid & 15;                  // 4-float chunk
        int s   = ((int*)(sb + OFF_SRC))[row];
        float w = ((float*)(sb + OFF_WG))[row];
        float4 v = reinterpret_cast<const float4*>(x)[(size_t)s * 16 + c4];
        if (L2) {
            int c = c4 * 4;
            v.x = fmaxf(v.x + bias[c + 0], 0.f);
            v.y = fmaxf(v.y + bias[c + 1], 0.f);
            v.z = fmaxf(v.z + bias[c + 2], 0.f);
            v.w = fmaxf(v.w + bias[c + 3], 0.f);
        }
        v.x *= w; v.y *= w; v.z *= w; v.w *= w;
        __nv_bfloat16 h0 = __float2bfloat16_rn(v.x), h1 = __float2bfloat16_rn(v.y);
        __nv_bfloat16 h2 = __float2bfloat16_rn(v.z), h3 = __float2bfloat16_rn(v.w);
        __nv_bfloat16 l0 = __float2bfloat16_rn(v.x - __bfloat162float(h0));
        __nv_bfloat16 l1 = __float2bfloat16_rn(v.y - __bfloat162float(h1));
        __nv_bfloat16 l2 = __float2bfloat16_rn(v.z - __bfloat162float(h2));
        __nv_bfloat16 l3 = __float2bfloat16_rn(v.w - __bfloat162float(h3));
        uint2 hv = make_uint2(((u32)__bfloat16_as_ushort(h1) << 16) | __bfloat16_as_ushort(h0),
                              ((u32)__bfloat16_as_ushort(h3) << 16) | __bfloat16_as_ushort(h2));
        uint2 lv = make_uint2(((u32)__bfloat16_as_ushort(l1) << 16) | __bfloat16_as_ushort(l0),
                              ((u32)__bfloat16_as_ushort(l3) << 16) | __bfloat16_as_ushort(l2));
        int c8 = c4 >> 1, half = c4 & 1;
        u32 off = (u32)(row * 128 + ((c8 ^ (row & 7)) << 4) + half * 8);
        *reinterpret_cast<uint2*>(sb + OFF_XHI + off) = hv;
        *reinterpret_cast<uint2*>(sb + OFF_XLO + off) = lv;
    }
    __syncthreads();

    const uint32_t xhi_base = sbase + OFF_XHI;
    const uint32_t xlo_base = sbase + OFF_XLO;
    const char* wh = sb + OFF_W;
    const char* wl = wh + 9216;

    float acc[2][8][4];
    #pragma unroll
    for (int mt = 0; mt < 2; ++mt)
        #pragma unroll
        for (int t = 0; t < 8; ++t)
            #pragma unroll
            for (int j = 0; j < 4; ++j) acc[mt][t][j] = 0.f;

    #pragma unroll
    for (int ks = 0; ks < 4; ++ks) {
        uint32_t ahi[2][4], alo[2][4];
        #pragma unroll
        for (int mt = 0; mt < 2; ++mt) {
            int row = wid * 32 + mt * 16 + (lane & 15);
            int c16 = ks * 2 + (lane >> 4);
            uint32_t off = (uint32_t)(row * 128 + ((c16 ^ (row & 7)) << 4));
            ldsm_x4(ahi[mt], xhi_base + off);
            ldsm_x4(alo[mt], xlo_base + off);
        }
        const int nb = (lane >> 2);
        const int kb = 2 * (lane & 3) + ks * 16;
        uint32_t bh[8][2], bl[8][2];
        #pragma unroll
        for (int t = 0; t < 8; ++t) {
            int o = nb + 8 * t;
            bh[t][0] = *reinterpret_cast<const uint32_t*>(wh + o * WPITCH + kb * 2);
            bh[t][1] = *reinterpret_cast<const uint32_t*>(wh + o * WPITCH + (kb + 8) * 2);
            bl[t][0] = *reinterpret_cast<const uint32_t*>(wl + o * WPITCH + kb * 2);
            bl[t][1] = *reinterpret_cast<const uint32_t*>(wl + o * WPITCH + (kb + 8) * 2);
        }
        #pragma unroll
        for (int mt = 0; mt < 2; ++mt)
            #pragma unroll
            for (int t = 0; t < 8; ++t) {
                mma_bf16(acc[mt][t], ahi[mt], bh[t]);
                mma_bf16(acc[mt][t], alo[mt], bh[t]);
                mma_bf16(acc[mt][t], ahi[mt], bl[t]);
            }
    }

    // stage output tile into smem (reuse X region), bank-swizzled
    __syncthreads();
    float* stg = reinterpret_cast<float*>(sb);
    #pragma unroll
    for (int mt = 0; mt < 2; ++mt) {
        int rA = wid * 32 + mt * 16 + (lane >> 2);
        int rB = rA + 8;
        int sw = (rA & 7) << 3;              // rB&7 == rA&7
        #pragma unroll
        for (int t = 0; t < 8; ++t) {
            int col = t * 8 + 2 * (lane & 3);
            *reinterpret_cast<float2*>(&stg[rA * 64 + (col ^ sw)]) =
                make_float2(acc[mt][t][0], acc[mt][t][1]);
            *reinterpret_cast<float2*>(&stg[rB * 64 + (col ^ sw)]) =
                make_float2(acc[mt][t][2], acc[mt][t][3]);
        }
    }
    __syncthreads();

    // vectorized L2-resident reductions into out[dst]
    #pragma unroll
    for (int p = 0; p < 16; ++p) {
        int row = p * 8 + (tid >> 4);
        if (row < cnt) {
            int c4 = tid & 15;
            int cc = (c4 * 4) ^ ((row & 7) << 3);
            float4 v = *reinterpret_cast<float4*>(&stg[row * 64 + cc]);
            int d = ((int*)(sb + OFF_DST))[row];
            float* pdst = &out[(size_t)d * DD + c4 * 4];
            asm volatile("red.global.add.v4.f32 [%0], {%1, %2, %3, %4};"
                         :: "l"(pdst), "f"(v.x), "f"(v.y), "f"(v.z), "f"(v.w) : "memory");
        }
    }
}

// ---------------- aux ----------------

__global__ void zero_x1_kernel(int n4)
{
    int i = blockIdx.x * blockDim.x + threadIdx.x;
    if (i < n4) reinterpret_cast<float4*>(g_x1)[i] = make_float4(0.f, 0.f, 0.f, 0.f);
}

__global__ void relu_bias_kernel(float* __restrict__ out,
                                 const float* __restrict__ bias, int n4)
{
    int f = blockIdx.x * blockDim.x + threadIdx.x;
    if (f >= n4) return;
    int c4 = (f & 15) << 2;
    float4 v = reinterpret_cast<float4*>(out)[f];
    v.x = fmaxf(v.x + bias[c4 + 0], 0.f);
    v.y = fmaxf(v.y + bias[c4 + 1], 0.f);
    v.z = fmaxf(v.z + bias[c4 + 2], 0.f);
    v.w = fmaxf(v.w + bias[c4 + 3], 0.f);
    reinterpret_cast<float4*>(out)[f] = v;
}

extern "C" void kernel_launch(void* const* d_in, const int* in_sizes, int n_in,
                              void* d_out, int out_size)
{
    const float* x   = (const float*)d_in[0];
    const int*   ei  = (const int*)  d_in[1];
    const int*   et  = (const int*)  d_in[2];
    const float* pl  = (const float*)d_in[3];
    const float* w1  = (const float*)d_in[4];
    const float* b1  = (const float*)d_in[5];
    const float* w2  = (const float*)d_in[6];
    const float* b2  = (const float*)d_in[7];

    const int N    = in_sizes[0] / DD;
    const int E0   = in_sizes[1] / 2;
    const int nTot = in_sizes[2];

    const int maxT  = (nTot + TILE_M - 1) / TILE_M + RR;
    const int sgrid = (nTot + 2047) / 2048;
    const int n4    = N * (DD / 4);

    cudaFuncSetAttribute(edge_mma<false>,
                         cudaFuncAttributeMaxDynamicSharedMemorySize, SMEM_BYTES);
    cudaFuncSetAttribute(edge_mma<true>,
                         cudaFuncAttributeMaxDynamicSharedMemorySize, SMEM_BYTES);

    // prep (once per launch): W conversion + counting sort by relation
    convert_W<<<32, 256>>>(w1, w2);
    init_cnt<<<1, 32>>>();
    hist_kernel<<<sgrid, 256>>>(et, nTot);
    scan_tiles<<<1, 32>>>();
    fill_kernel<<<sgrid, 256>>>(ei, et, pl, E0, nTot);

    // layer 1: fused transform+scatter into g_x1
    zero_x1_kernel<<<(n4 + 255) / 256, 256>>>(n4);
    edge_mma<false><<<maxT, 128, SMEM_BYTES>>>(x, nullptr, nullptr, 1, N);

    // layer 2: relu(x1+b1) fused into gather; output into d_out
    cudaMemsetAsync(d_out, 0, (size_t)N * DD * sizeof(float));
    edge_mma<true><<<maxT, 128, SMEM_BYTES>>>(nullptr, b1, (float*)d_out, 0, N);
    relu_bias_kernel<<<(n4 + 255) / 256, 256>>>((float*)d_out, b2, n4);
}

// round 6
// speedup vs baseline: 1.8053x; 1.0565x over previous
#include <cuda_runtime.h>
#include <cuda_bf16.h>
#include <cstdint>

#define DD 64
#define RR 16
#define MAXE 851968
#define TILE_M 128

typedef unsigned int u32;

// ---- static scratch (allocation-free rule) ----
__device__ float g_x1[(size_t)50048 * DD];                 // layer-1 output (12.8MB, L2-resident)
__device__ __nv_bfloat16 g_xs[(size_t)50048 * 128];        // per-node split: [n][0:64]=hi, [64:128]=lo
__device__ __nv_bfloat16 g_Wt[2][RR][2][DD][DD];           // [layer][r][hi/lo][o][k]
__device__ int   g_src[MAXE];
__device__ int   g_dstA[MAXE];
__device__ float g_wgt[MAXE];
__device__ u32   g_rcnt[RR];
__device__ u32   g_roff[RR + 1];
__device__ u32   g_pos[RR];
__device__ u32   g_tiles[8192];
__device__ u32   g_ntiles;

__device__ __forceinline__ uint32_t smem_u32(const void* p) {
    uint32_t a;
    asm("{ .reg .u64 t; cvta.to.shared.u64 t, %1; cvt.u32.u64 %0, t; }" : "=r"(a) : "l"(p));
    return a;
}

__device__ __forceinline__ void ldsm_x4(uint32_t* r, uint32_t addr) {
    asm volatile("ldmatrix.sync.aligned.m8n8.x4.shared.b16 {%0,%1,%2,%3}, [%4];"
                 : "=r"(r[0]), "=r"(r[1]), "=r"(r[2]), "=r"(r[3]) : "r"(addr));
}

__device__ __forceinline__ void mma_bf16(float* c, const uint32_t* a, const uint32_t* b) {
    asm volatile(
        "mma.sync.aligned.m16n8k16.row.col.f32.bf16.bf16.f32 "
        "{%0,%1,%2,%3}, {%4,%5,%6,%7}, {%8,%9}, {%0,%1,%2,%3};"
        : "+f"(c[0]), "+f"(c[1]), "+f"(c[2]), "+f"(c[3])
        : "r"(a[0]), "r"(a[1]), "r"(a[2]), "r"(a[3]), "r"(b[0]), "r"(b[1]));
}

__device__ __forceinline__ u32 pack_bf16x2(float a, float b) {
    u32 r; asm("cvt.rn.bf16x2.f32 %0, %1, %2;" : "=r"(r) : "f"(b), "f"(a)); return r;
}

// ---------------- W pre-convert (+ zero rcnt) ----------------
__global__ void convert_W(const float* __restrict__ W1, const float* __restrict__ W2)
{
    const int lr = blockIdx.x;               // 0..31
    const int layer = lr >> 4, r = lr & 15;
    if (lr == 0 && threadIdx.x < RR) g_rcnt[threadIdx.x] = 0;
    const float* Wr = (layer ? W2 : W1) + (size_t)r * DD * DD;
    __shared__ float tile[DD][DD + 1];
    const int tid = threadIdx.x;             // 256
    #pragma unroll
    for (int it = 0; it < 16; ++it) {
        int idx = it * 256 + tid;
        tile[idx >> 6][idx & 63] = Wr[idx];  // tile[i][o]
    }
    __syncthreads();
    #pragma unroll
    for (int it = 0; it < 16; ++it) {
        int idx = it * 256 + tid;
        int o = idx >> 6, k = idx & 63;
        float w = tile[k][o];
        __nv_bfloat16 h = __float2bfloat16_rn(w);
        __nv_bfloat16 l = __float2bfloat16_rn(w - __bfloat162float(h));
        g_Wt[layer][r][0][o][k] = h;
        g_Wt[layer][r][1][o][k] = l;
    }
}

// ---------------- per-node bf16 hi/lo split ----------------
// L2 variant reads g_x1 and fuses relu(x + bias).
template<bool L2>
__global__ void split_x(const float* __restrict__ x_in,
                        const float* __restrict__ bias, int N)
{
    const int idx = blockIdx.x * blockDim.x + threadIdx.x;   // one per 8 floats
    const int row = idx >> 3;
    const int c8  = idx & 7;
    if (row >= N) return;
    const float* src = L2 ? (const float*)g_x1 : x_in;
    float4 v0 = reinterpret_cast<const float4*>(src)[(size_t)row * 16 + c8 * 2];
    float4 v1 = reinterpret_cast<const float4*>(src)[(size_t)row * 16 + c8 * 2 + 1];
    if (L2) {
        int c = c8 * 8;
        v0.x = fmaxf(v0.x + bias[c+0], 0.f); v0.y = fmaxf(v0.y + bias[c+1], 0.f);
        v0.z = fmaxf(v0.z + bias[c+2], 0.f); v0.w = fmaxf(v0.w + bias[c+3], 0.f);
        v1.x = fmaxf(v1.x + bias[c+4], 0.f); v1.y = fmaxf(v1.y + bias[c+5], 0.f);
        v1.z = fmaxf(v1.z + bias[c+6], 0.f); v1.w = fmaxf(v1.w + bias[c+7], 0.f);
    }
    float f[8] = {v0.x, v0.y, v0.z, v0.w, v1.x, v1.y, v1.z, v1.w};
    u32 hi[4], lo[4];
    #pragma unroll
    for (int j = 0; j < 4; ++j) {
        hi[j] = pack_bf16x2(f[2*j], f[2*j+1]);
        float h0 = __uint_as_float(hi[j] << 16);
        float h1 = __uint_as_float(hi[j] & 0xFFFF0000u);
        lo[j] = pack_bf16x2(f[2*j] - h0, f[2*j+1] - h1);
    }
    uint4* dst = reinterpret_cast<uint4*>(g_xs) + (size_t)row * 16;
    dst[c8]     = make_uint4(hi[0], hi[1], hi[2], hi[3]);
    dst[c8 + 8] = make_uint4(lo[0], lo[1], lo[2], lo[3]);
}

// ---------------- counting sort by relation ----------------

__global__ void hist_kernel(const int* __restrict__ et, int nTot)
{
    __shared__ u32 h[RR];
    const int tid = threadIdx.x;
    if (tid < RR) h[tid] = 0;
    __syncthreads();
    const int base = blockIdx.x * 2048;
    #pragma unroll
    for (int j = 0; j < 8; ++j) {
        int e = base + j * 256 + tid;
        if (e < nTot) atomicAdd(&h[et[e] & 15], 1u);
    }
    __syncthreads();
    if (tid < RR && h[tid]) atomicAdd(&g_rcnt[tid], h[tid]);
}

__global__ void scan_tiles()   // 512 threads
{
    __shared__ u32 s_off[RR];
    __shared__ u32 s_tb[RR + 1];
    if (threadIdx.x < 32) {
        const int lane = threadIdx.x;
        u32 c = (lane < RR) ? g_rcnt[lane] : 0;
        u32 x = c;
        #pragma unroll
        for (int s = 1; s < 16; s <<= 1) {
            u32 y = __shfl_up_sync(0xFFFFFFFFu, x, s);
            if (lane >= s) x += y;
        }
        if (lane < RR) { g_roff[lane] = x - c; g_pos[lane] = x - c; s_off[lane] = x - c; }
        if (lane == RR - 1) g_roff[RR] = x;

        u32 nt = (c + TILE_M - 1) / TILE_M;
        u32 tx = nt;
        #pragma unroll
        for (int s = 1; s < 16; s <<= 1) {
            u32 y = __shfl_up_sync(0xFFFFFFFFu, tx, s);
            if (lane >= s) tx += y;
        }
        if (lane < RR) s_tb[lane] = tx - nt;
        if (lane == RR - 1) { s_tb[RR] = tx; g_ntiles = tx; }
    }
    __syncthreads();
    const u32 total = s_tb[RR];
    for (u32 t = threadIdx.x; t < total; t += blockDim.x) {
        int rel = 0;
        #pragma unroll
        for (int r = 1; r < RR; ++r) if (t >= s_tb[r]) rel = r;
        g_tiles[t] = (s_off[rel] + (t - s_tb[rel]) * TILE_M) | ((u32)rel << 24);
    }
}

__global__ void fill_kernel(const int* __restrict__ ei, const int* __restrict__ et,
                            const float* __restrict__ pl, int E0, int nTot)
{
    __shared__ u32 h[RR];
    __shared__ u32 base16[RR];
    const int tid = threadIdx.x;
    if (tid < RR) h[tid] = 0;
    __syncthreads();
    const int b = blockIdx.x * 2048;
    int rel[8]; u32 rank[8];
    #pragma unroll
    for (int j = 0; j < 8; ++j) {
        int e = b + j * 256 + tid;
        rel[j] = -1;
        if (e < nTot) { rel[j] = et[e] & 15; rank[j] = atomicAdd(&h[rel[j]], 1u); }
    }
    __syncthreads();
    if (tid < RR) base16[tid] = h[tid] ? atomicAdd(&g_pos[tid], h[tid]) : 0u;
    __syncthreads();
    #pragma unroll
    for (int j = 0; j < 8; ++j) {
        if (rel[j] >= 0) {
            int e = b + j * 256 + tid;
            u32 p = base16[rel[j]] + rank[j];
            int s, d;
            if (e < E0) { s = ei[e]; d = ei[E0 + e]; }
            else        { s = e - E0; d = s; }
            g_src[p]  = s;
            g_dstA[p] = d;
            g_wgt[p]  = 1.0f / fmaxf(pl[e], 1e-9f);
        }
    }
}

// ---------------- fused edge GEMM + scatter ----------------
// One CTA = 128 same-relation edges: copy pre-split bf16 rows from g_xs into
// LDSM-swizzled smem, 3-term HMMA vs W_r, scale by w in fp32 epilogue,
// red.global.add.v4 into out[dst].

#define WPITCH 144
#define OFF_XHI 0
#define OFF_XLO 16384
#define OFF_W   32768
#define OFF_SRC 51200
#define OFF_DST 51712
#define OFF_WG  52224
#define SMEM_BYTES 52736

__global__ void __launch_bounds__(128, 3) edge_mma(
    int layer, float* __restrict__ out_p, int toG)
{
    const u32 bid = blockIdx.x;
    if (bid >= g_ntiles) return;

    extern __shared__ char sb[];
    const uint32_t sbase = smem_u32(sb);

    const u32 tdesc = g_tiles[bid];
    const int start = (int)(tdesc & 0xFFFFFF);
    const int rel   = (int)(tdesc >> 24);
    const int cnt   = min(TILE_M, (int)g_roff[rel + 1] - start);

    float* __restrict__ out = toG ? (float*)g_x1 : out_p;

    const int tid  = threadIdx.x;
    const int wid  = tid >> 5;
    const int lane = tid & 31;

    // stage edge meta (invalid rows -> src 0, w 0)
    if (tid < TILE_M) {
        int s = 0, d = 0; float w = 0.f;
        if (tid < cnt) { s = g_src[start + tid]; d = g_dstA[start + tid]; w = g_wgt[start + tid]; }
        ((int*)(sb + OFF_SRC))[tid] = s;
        ((int*)(sb + OFF_DST))[tid] = d;
        ((float*)(sb + OFF_WG))[tid] = w;
    }

    // stage W_r (bf16 hi/lo, padded rows)
    {
        const uint4* src = reinterpret_cast<const uint4*>(&g_Wt[layer][rel][0][0][0]);
        #pragma unroll
        for (int it = 0; it < 8; ++it) {
            int idx  = it * 128 + tid;       // 1024 uint4 (hi 512, lo 512)
            int half = idx >> 9;
            int rem  = idx & 511;
            int o    = rem >> 3;
            int j    = rem & 7;
            *reinterpret_cast<uint4*>(sb + OFF_W + half * 9216 + o * WPITCH + j * 16) = src[idx];
        }
    }
    __syncthreads();

    // gather pre-split rows (pure uint4 copies), LDSM swizzle
    #pragma unroll
    for (int p = 0; p < 16; ++p) {
        int row = p * 8 + (tid >> 4);
        int c   = tid & 15;                  // chunk: 0..7 hi, 8..15 lo
        int s   = ((int*)(sb + OFF_SRC))[row];
        uint4 v = reinterpret_cast<const uint4*>(g_xs)[(size_t)s * 16 + c];
        int base = (c < 8) ? OFF_XHI : OFF_XLO;
        int c8   = c & 7;
        u32 off  = (u32)(row * 128 + ((c8 ^ (row & 7)) << 4));
        *reinterpret_cast<uint4*>(sb + base + off) = v;
    }
    __syncthreads();

    const uint32_t xhi_base = sbase + OFF_XHI;
    const uint32_t xlo_base = sbase + OFF_XLO;
    const char* wh = sb + OFF_W;
    const char* wl = wh + 9216;

    float acc[2][8][4];
    #pragma unroll
    for (int mt = 0; mt < 2; ++mt)
        #pragma unroll
        for (int t = 0; t < 8; ++t)
            #pragma unroll
            for (int j = 0; j < 4; ++j) acc[mt][t][j] = 0.f;

    #pragma unroll
    for (int ks = 0; ks < 4; ++ks) {
        uint32_t ahi[2][4], alo[2][4];
        #pragma unroll
        for (int mt = 0; mt < 2; ++mt) {
            int row = wid * 32 + mt * 16 + (lane & 15);
            int c16 = ks * 2 + (lane >> 4);
            uint32_t off = (uint32_t)(row * 128 + ((c16 ^ (row & 7)) << 4));
            ldsm_x4(ahi[mt], xhi_base + off);
            ldsm_x4(alo[mt], xlo_base + off);
        }
        const int nb = (lane >> 2);
        const int kb = 2 * (lane & 3) + ks * 16;
        uint32_t bh[8][2], bl[8][2];
        #pragma unroll
        for (int t = 0; t < 8; ++t) {
            int o = nb + 8 * t;
            bh[t][0] = *reinterpret_cast<const uint32_t*>(wh + o * WPITCH + kb * 2);
            bh[t][1] = *reinterpret_cast<const uint32_t*>(wh + o * WPITCH + (kb + 8) * 2);
            bl[t][0] = *reinterpret_cast<const uint32_t*>(wl + o * WPITCH + kb * 2);
            bl[t][1] = *reinterpret_cast<const uint32_t*>(wl + o * WPITCH + (kb + 8) * 2);
        }
        #pragma unroll
        for (int mt = 0; mt < 2; ++mt)
            #pragma unroll
            for (int t = 0; t < 8; ++t) {
                mma_bf16(acc[mt][t], ahi[mt], bh[t]);
                mma_bf16(acc[mt][t], alo[mt], bh[t]);
                mma_bf16(acc[mt][t], ahi[mt], bl[t]);
            }
    }

    // stage output tile into smem (reuse X region), bank-swizzled
    __syncthreads();
    float* stg = reinterpret_cast<float*>(sb);
    #pragma unroll
    for (int mt = 0; mt < 2; ++mt) {
        int rA = wid * 32 + mt * 16 + (lane >> 2);
        int rB = rA + 8;
        int sw = (rA & 7) << 3;
        #pragma unroll
        for (int t = 0; t < 8; ++t) {
            int col = t * 8 + 2 * (lane & 3);
            *reinterpret_cast<float2*>(&stg[rA * 64 + (col ^ sw)]) =
                make_float2(acc[mt][t][0], acc[mt][t][1]);
            *reinterpret_cast<float2*>(&stg[rB * 64 + (col ^ sw)]) =
                make_float2(acc[mt][t][2], acc[mt][t][3]);
        }
    }
    __syncthreads();

    // scale by 1/pl in fp32 and reduce into out[dst] (L2-resident)
    #pragma unroll
    for (int p = 0; p < 16; ++p) {
        int row = p * 8 + (tid >> 4);
        if (row < cnt) {
            int c4 = tid & 15;
            int cc = (c4 * 4) ^ ((row & 7) << 3);
            float w = ((float*)(sb + OFF_WG))[row];
            float4 v = *reinterpret_cast<float4*>(&stg[row * 64 + cc]);
            v.x *= w; v.y *= w; v.z *= w; v.w *= w;
            int d = ((int*)(sb + OFF_DST))[row];
            float* pdst = &out[(size_t)d * DD + c4 * 4];
            asm volatile("red.global.add.v4.f32 [%0], {%1, %2, %3, %4};"
                         :: "l"(pdst), "f"(v.x), "f"(v.y), "f"(v.z), "f"(v.w) : "memory");
        }
    }
}

// ---------------- aux ----------------

__global__ void zero_x1_kernel(int n4)
{
    int i = blockIdx.x * blockDim.x + threadIdx.x;
    if (i < n4) reinterpret_cast<float4*>(g_x1)[i] = make_float4(0.f, 0.f, 0.f, 0.f);
}

__global__ void relu_bias_kernel(float* __restrict__ out,
                                 const float* __restrict__ bias, int n4)
{
    int f = blockIdx.x * blockDim.x + threadIdx.x;
    if (f >= n4) return;
    int c4 = (f & 15) << 2;
    float4 v = reinterpret_cast<float4*>(out)[f];
    v.x = fmaxf(v.x + bias[c4 + 0], 0.f);
    v.y = fmaxf(v.y + bias[c4 + 1], 0.f);
    v.z = fmaxf(v.z + bias[c4 + 2], 0.f);
    v.w = fmaxf(v.w + bias[c4 + 3], 0.f);
    reinterpret_cast<float4*>(out)[f] = v;
}

extern "C" void kernel_launch(void* const* d_in, const int* in_sizes, int n_in,
                              void* d_out, int out_size)
{
    const float* x   = (const float*)d_in[0];
    const int*   ei  = (const int*)  d_in[1];
    const int*   et  = (const int*)  d_in[2];
    const float* pl  = (const float*)d_in[3];
    const float* w1  = (const float*)d_in[4];
    const float* b1  = (const float*)d_in[5];
    const float* w2  = (const float*)d_in[6];
    const float* b2  = (const float*)d_in[7];

    const int N    = in_sizes[0] / DD;
    const int E0   = in_sizes[1] / 2;
    const int nTot = in_sizes[2];

    const int maxT  = (nTot + TILE_M - 1) / TILE_M + RR;
    const int sgrid = (nTot + 2047) / 2048;
    const int n4    = N * (DD / 4);
    const int splitG = (N * 8 + 255) / 256;

    cudaFuncSetAttribute(edge_mma,
                         cudaFuncAttributeMaxDynamicSharedMemorySize, SMEM_BYTES);

    // prep: W conversion (+rcnt zero), counting sort, per-node x split
    convert_W<<<32, 256>>>(w1, w2);
    hist_kernel<<<sgrid, 256>>>(et, nTot);
    scan_tiles<<<1, 512>>>();
    fill_kernel<<<sgrid, 256>>>(ei, et, pl, E0, nTot);
    split_x<false><<<splitG, 256>>>(x, nullptr, N);

    // layer 1: fused transform+scatter into g_x1
    zero_x1_kernel<<<(n4 + 255) / 256, 256>>>(n4);
    edge_mma<<<maxT, 128, SMEM_BYTES>>>(0, nullptr, 1);

    // layer 2: split relu(x1+b1), then fused transform+scatter into d_out
    split_x<true><<<splitG, 256>>>(nullptr, b1, N);
    cudaMemsetAsync(d_out, 0, (size_t)N * DD * sizeof(float));
    edge_mma<<<maxT, 128, SMEM_BYTES>>>(1, (float*)d_out, 0);
    relu_bias_kernel<<<(n4 + 255) / 256, 256>>>((float*)d_out, b2, n4);
}

// round 7
// speedup vs baseline: 1.8710x; 1.0364x over previous
#include <cuda_runtime.h>
#include <cuda_bf16.h>
#include <cstdint>

#define DD 64
#define RR 16
#define MAXE 851968
#define TILE_M 128

typedef unsigned int u32;

// ---- static scratch (allocation-free rule) ----
__device__ float g_x1[(size_t)50048 * DD];                 // layer-1 output (12.8MB, L2-resident)
__device__ __nv_bfloat16 g_xs[(size_t)50048 * 128];        // per-node split: [n][0:64]=hi, [64:128]=lo
__device__ __nv_bfloat16 g_Wt[2][RR][2][DD][DD];           // [layer][r][hi/lo][o][k]
__device__ int   g_src[MAXE];
__device__ int   g_dstA[MAXE];
__device__ float g_wgt[MAXE];
__device__ u32   g_rcnt[RR];
__device__ u32   g_roff[RR + 1];
__device__ u32   g_pos[RR];
__device__ u32   g_tiles[8192];
__device__ u32   g_ntiles;

__device__ __forceinline__ uint32_t smem_u32(const void* p) {
    uint32_t a;
    asm("{ .reg .u64 t; cvta.to.shared.u64 t, %1; cvt.u32.u64 %0, t; }" : "=r"(a) : "l"(p));
    return a;
}

__device__ __forceinline__ void ldsm_x4(uint32_t* r, uint32_t addr) {
    asm volatile("ldmatrix.sync.aligned.m8n8.x4.shared.b16 {%0,%1,%2,%3}, [%4];"
                 : "=r"(r[0]), "=r"(r[1]), "=r"(r[2]), "=r"(r[3]) : "r"(addr));
}

__device__ __forceinline__ void mma_bf16(float* c, const uint32_t* a, const uint32_t* b) {
    asm volatile(
        "mma.sync.aligned.m16n8k16.row.col.f32.bf16.bf16.f32 "
        "{%0,%1,%2,%3}, {%4,%5,%6,%7}, {%8,%9}, {%0,%1,%2,%3};"
        : "+f"(c[0]), "+f"(c[1]), "+f"(c[2]), "+f"(c[3])
        : "r"(a[0]), "r"(a[1]), "r"(a[2]), "r"(a[3]), "r"(b[0]), "r"(b[1]));
}

__device__ __forceinline__ u32 pack_bf16x2(float a, float b) {
    u32 r; asm("cvt.rn.bf16x2.f32 %0, %1, %2;" : "=r"(r) : "f"(b), "f"(a)); return r;
}

__device__ __forceinline__ void cpasync16(u32 smem, const void* gmem) {
    asm volatile("cp.async.cg.shared.global [%0], [%1], 16;" :: "r"(smem), "l"(gmem) : "memory");
}

// ---------------- W pre-convert (+ zero rcnt) ----------------
__global__ void convert_W(const float* __restrict__ W1, const float* __restrict__ W2)
{
    const int lr = blockIdx.x;               // 0..31
    const int layer = lr >> 4, r = lr & 15;
    if (lr == 0 && threadIdx.x < RR) g_rcnt[threadIdx.x] = 0;
    const float* Wr = (layer ? W2 : W1) + (size_t)r * DD * DD;
    __shared__ float tile[DD][DD + 1];
    const int tid = threadIdx.x;             // 256
    #pragma unroll
    for (int it = 0; it < 16; ++it) {
        int idx = it * 256 + tid;
        tile[idx >> 6][idx & 63] = Wr[idx];  // tile[i][o]
    }
    __syncthreads();
    #pragma unroll
    for (int it = 0; it < 16; ++it) {
        int idx = it * 256 + tid;
        int o = idx >> 6, k = idx & 63;
        float w = tile[k][o];
        __nv_bfloat16 h = __float2bfloat16_rn(w);
        __nv_bfloat16 l = __float2bfloat16_rn(w - __bfloat162float(h));
        g_Wt[layer][r][0][o][k] = h;
        g_Wt[layer][r][1][o][k] = l;
    }
}

// ---------------- per-node bf16 hi/lo split ----------------
template<bool L2>
__global__ void split_x(const float* __restrict__ x_in,
                        const float* __restrict__ bias, int N)
{
    const int idx = blockIdx.x * blockDim.x + threadIdx.x;   // one per 8 floats
    const int row = idx >> 3;
    const int c8  = idx & 7;
    if (row >= N) return;
    const float* src = L2 ? (const float*)g_x1 : x_in;
    float4 v0 = reinterpret_cast<const float4*>(src)[(size_t)row * 16 + c8 * 2];
    float4 v1 = reinterpret_cast<const float4*>(src)[(size_t)row * 16 + c8 * 2 + 1];
    if (L2) {
        int c = c8 * 8;
        v0.x = fmaxf(v0.x + bias[c+0], 0.f); v0.y = fmaxf(v0.y + bias[c+1], 0.f);
        v0.z = fmaxf(v0.z + bias[c+2], 0.f); v0.w = fmaxf(v0.w + bias[c+3], 0.f);
        v1.x = fmaxf(v1.x + bias[c+4], 0.f); v1.y = fmaxf(v1.y + bias[c+5], 0.f);
        v1.z = fmaxf(v1.z + bias[c+6], 0.f); v1.w = fmaxf(v1.w + bias[c+7], 0.f);
    }
    float f[8] = {v0.x, v0.y, v0.z, v0.w, v1.x, v1.y, v1.z, v1.w};
    u32 hi[4], lo[4];
    #pragma unroll
    for (int j = 0; j < 4; ++j) {
        hi[j] = pack_bf16x2(f[2*j], f[2*j+1]);
        float h0 = __uint_as_float(hi[j] << 16);
        float h1 = __uint_as_float(hi[j] & 0xFFFF0000u);
        lo[j] = pack_bf16x2(f[2*j] - h0, f[2*j+1] - h1);
    }
    uint4* dst = reinterpret_cast<uint4*>(g_xs) + (size_t)row * 16;
    dst[c8]     = make_uint4(hi[0], hi[1], hi[2], hi[3]);
    dst[c8 + 8] = make_uint4(lo[0], lo[1], lo[2], lo[3]);
}

// ---------------- counting sort by relation ----------------

__global__ void hist_kernel(const int* __restrict__ et, int nTot)
{
    __shared__ u32 h[RR];
    const int tid = threadIdx.x;
    if (tid < RR) h[tid] = 0;
    __syncthreads();
    const int base = blockIdx.x * 1024;
    #pragma unroll
    for (int j = 0; j < 4; ++j) {
        int e = base + j * 256 + tid;
        if (e < nTot) atomicAdd(&h[et[e] & 15], 1u);
    }
    __syncthreads();
    if (tid < RR && h[tid]) atomicAdd(&g_rcnt[tid], h[tid]);
}

__global__ void scan_tiles()   // 512 threads
{
    __shared__ u32 s_off[RR];
    __shared__ u32 s_tb[RR + 1];
    if (threadIdx.x < 32) {
        const int lane = threadIdx.x;
        u32 c = (lane < RR) ? g_rcnt[lane] : 0;
        u32 x = c;
        #pragma unroll
        for (int s = 1; s < 16; s <<= 1) {
            u32 y = __shfl_up_sync(0xFFFFFFFFu, x, s);
            if (lane >= s) x += y;
        }
        if (lane < RR) { g_roff[lane] = x - c; g_pos[lane] = x - c; s_off[lane] = x - c; }
        if (lane == RR - 1) g_roff[RR] = x;

        u32 nt = (c + TILE_M - 1) / TILE_M;
        u32 tx = nt;
        #pragma unroll
        for (int s = 1; s < 16; s <<= 1) {
            u32 y = __shfl_up_sync(0xFFFFFFFFu, tx, s);
            if (lane >= s) tx += y;
        }
        if (lane < RR) s_tb[lane] = tx - nt;
        if (lane == RR - 1) { s_tb[RR] = tx; g_ntiles = tx; }
    }
    __syncthreads();
    const u32 total = s_tb[RR];
    for (u32 t = threadIdx.x; t < total; t += blockDim.x) {
        int rel = 0;
        #pragma unroll
        for (int r = 1; r < RR; ++r) if (t >= s_tb[r]) rel = r;
        g_tiles[t] = (s_off[rel] + (t - s_tb[rel]) * TILE_M) | ((u32)rel << 24);
    }
}

__global__ void fill_kernel(const int* __restrict__ ei, const int* __restrict__ et,
                            const float* __restrict__ pl, int E0, int nTot)
{
    __shared__ u32 h[RR];
    __shared__ u32 base16[RR];
    const int tid = threadIdx.x;
    if (tid < RR) h[tid] = 0;
    __syncthreads();
    const int b = blockIdx.x * 1024;
    int rel[4]; u32 rank[4];
    #pragma unroll
    for (int j = 0; j < 4; ++j) {
        int e = b + j * 256 + tid;
        rel[j] = -1;
        if (e < nTot) { rel[j] = et[e] & 15; rank[j] = atomicAdd(&h[rel[j]], 1u); }
    }
    __syncthreads();
    if (tid < RR) base16[tid] = h[tid] ? atomicAdd(&g_pos[tid], h[tid]) : 0u;
    __syncthreads();
    #pragma unroll
    for (int j = 0; j < 4; ++j) {
        if (rel[j] >= 0) {
            int e = b + j * 256 + tid;
            u32 p = base16[rel[j]] + rank[j];
            int s, d;
            if (e < E0) { s = ei[e]; d = ei[E0 + e]; }
            else        { s = e - E0; d = s; }
            g_src[p]  = s;
            g_dstA[p] = d;
            g_wgt[p]  = 1.0f / fmaxf(pl[e], 1e-9f);
        }
    }
}

// ---------------- persistent fused edge GEMM + scatter ----------------
// Each CTA owns a contiguous chunk of 128-edge tiles (mostly same relation).
// Double-buffered: cp.async gathers for tile t+1 overlap the MMA/epilogue of t.

#define WPITCH 144
#define OFF_X    0                 // 2 bufs x 32768 (hi 16K + lo 16K each)
#define OFF_W    65536             // hi 9216 + lo 9216
#define OFF_META 83968             // d[2][128] int, w[2][128] float
#define SMEM_BYTES 86016
#define GRID_MMA 296

__global__ void __launch_bounds__(128, 2) edge_mma(
    int layer, float* __restrict__ out_p, int toG)
{
    extern __shared__ char sb[];
    const uint32_t sbase = smem_u32(sb);
    float* __restrict__ out = toG ? (float*)g_x1 : out_p;

    const int tid  = threadIdx.x;
    const int wid  = tid >> 5;
    const int lane = tid & 31;

    const u32 ntiles = g_ntiles;
    const u32 chunk  = (ntiles + gridDim.x - 1) / gridDim.x;
    const u32 t0 = blockIdx.x * chunk;
    const u32 t1 = min(t0 + chunk, ntiles);
    if (t0 >= t1) return;

    int*   meta_d = (int*)(sb + OFF_META);
    float* meta_w = (float*)(sb + OFF_META + 1024);

    // ---- prologue: prefetch tile t0 into buf 0 ----
    {
        u32 td = g_tiles[t0];
        int start = (int)(td & 0xFFFFFF);
        int rel   = (int)(td >> 24);
        int cnt   = min(TILE_M, (int)g_roff[rel + 1] - start);
        int s = 0, d = 0; float w = 0.f;
        if (tid < cnt) { s = g_src[start + tid]; d = g_dstA[start + tid]; w = g_wgt[start + tid]; }
        meta_d[tid] = d; meta_w[tid] = w;
        const char* gp = (const char*)g_xs + (size_t)s * 256;
        const u32 xb = sbase + OFF_X;
        #pragma unroll
        for (int c = 0; c < 8; ++c) {
            u32 so = (u32)(tid * 128 + ((c ^ (tid & 7)) << 4));
            cpasync16(xb + so,         gp + c * 16);        // hi
            cpasync16(xb + 16384 + so, gp + 128 + c * 16);  // lo
        }
        asm volatile("cp.async.commit_group;" ::: "memory");
    }

    int cur_rel = -1;

    for (u32 t = t0; t < t1; ++t) {
        const int buf = (int)((t - t0) & 1);
        const u32 td = g_tiles[t];
        const int start = (int)(td & 0xFFFFFF);
        const int rel   = (int)(td >> 24);
        const int cnt   = min(TILE_M, (int)g_roff[rel + 1] - start);

        asm volatile("cp.async.wait_group 0;" ::: "memory");

        if (rel != cur_rel) {
            const uint4* wsrc = reinterpret_cast<const uint4*>(&g_Wt[layer][rel][0][0][0]);
            #pragma unroll
            for (int it = 0; it < 8; ++it) {
                int idx  = it * 128 + tid;
                int half = idx >> 9;
                int rem  = idx & 511;
                int o    = rem >> 3;
                int j    = rem & 7;
                *reinterpret_cast<uint4*>(sb + OFF_W + half * 9216 + o * WPITCH + j * 16) = wsrc[idx];
            }
            cur_rel = rel;
        }
        __syncthreads();   // gathers for buf visible; W ready; prev epilogue done

        // issue meta LDGs for t+1 (latency hidden under MMA)
        const bool has_next = (t + 1 < t1);
        int ns = 0, nd = 0; float nw = 0.f;
        if (has_next) {
            u32 td2 = g_tiles[t + 1];
            int nstart = (int)(td2 & 0xFFFFFF);
            int nrel   = (int)(td2 >> 24);
            int ncnt   = min(TILE_M, (int)g_roff[nrel + 1] - nstart);
            if (tid < ncnt) {
                ns = g_src[nstart + tid];
                nd = g_dstA[nstart + tid];
                nw = g_wgt[nstart + tid];
            }
        }

        // ---- MMA on buf ----
        const uint32_t xhi_base = sbase + OFF_X + buf * 32768;
        const uint32_t xlo_base = xhi_base + 16384;
        const char* wh = sb + OFF_W;
        const char* wl = wh + 9216;

        float acc[2][8][4];
        #pragma unroll
        for (int mt = 0; mt < 2; ++mt)
            #pragma unroll
            for (int tt = 0; tt < 8; ++tt)
                #pragma unroll
                for (int j = 0; j < 4; ++j) acc[mt][tt][j] = 0.f;

        #pragma unroll
        for (int ks = 0; ks < 4; ++ks) {
            uint32_t ahi[2][4], alo[2][4];
            #pragma unroll
            for (int mt = 0; mt < 2; ++mt) {
                int row = wid * 32 + mt * 16 + (lane & 15);
                int c16 = ks * 2 + (lane >> 4);
                uint32_t off = (uint32_t)(row * 128 + ((c16 ^ (row & 7)) << 4));
                ldsm_x4(ahi[mt], xhi_base + off);
                ldsm_x4(alo[mt], xlo_base + off);
            }
            const int nb = (lane >> 2);
            const int kb = 2 * (lane & 3) + ks * 16;
            uint32_t bh[8][2], bl[8][2];
            #pragma unroll
            for (int tt = 0; tt < 8; ++tt) {
                int o = nb + 8 * tt;
                bh[tt][0] = *reinterpret_cast<const uint32_t*>(wh + o * WPITCH + kb * 2);
                bh[tt][1] = *reinterpret_cast<const uint32_t*>(wh + o * WPITCH + (kb + 8) * 2);
                bl[tt][0] = *reinterpret_cast<const uint32_t*>(wl + o * WPITCH + kb * 2);
                bl[tt][1] = *reinterpret_cast<const uint32_t*>(wl + o * WPITCH + (kb + 8) * 2);
            }
            #pragma unroll
            for (int mt = 0; mt < 2; ++mt)
                #pragma unroll
                for (int tt = 0; tt < 8; ++tt) {
                    mma_bf16(acc[mt][tt], ahi[mt], bh[tt]);
                    mma_bf16(acc[mt][tt], alo[mt], bh[tt]);
                    mma_bf16(acc[mt][tt], ahi[mt], bl[tt]);
                }
        }

        // ---- issue gathers for t+1 into buf^1 (overlap with stg/epilogue) ----
        if (has_next) {
            meta_d[(buf ^ 1) * 128 + tid] = nd;
            meta_w[(buf ^ 1) * 128 + tid] = nw;
            const char* gp = (const char*)g_xs + (size_t)ns * 256;
            const u32 xb = sbase + OFF_X + (buf ^ 1) * 32768;
            #pragma unroll
            for (int c = 0; c < 8; ++c) {
                u32 so = (u32)(tid * 128 + ((c ^ (tid & 7)) << 4));
                cpasync16(xb + so,         gp + c * 16);
                cpasync16(xb + 16384 + so, gp + 128 + c * 16);
            }
        }
        asm volatile("cp.async.commit_group;" ::: "memory");

        __syncthreads();   // all MMA reads of buf done -> reuse as staging

        float* stg = reinterpret_cast<float*>(sb + OFF_X + buf * 32768);
        #pragma unroll
        for (int mt = 0; mt < 2; ++mt) {
            int rA = wid * 32 + mt * 16 + (lane >> 2);
            int rB = rA + 8;
            int sw = (rA & 7) << 3;
            #pragma unroll
            for (int tt = 0; tt < 8; ++tt) {
                int col = tt * 8 + 2 * (lane & 3);
                *reinterpret_cast<float2*>(&stg[rA * 64 + (col ^ sw)]) =
                    make_float2(acc[mt][tt][0], acc[mt][tt][1]);
                *reinterpret_cast<float2*>(&stg[rB * 64 + (col ^ sw)]) =
                    make_float2(acc[mt][tt][2], acc[mt][tt][3]);
            }
        }
        __syncthreads();

        // scale by 1/pl in fp32 and reduce into out[dst] (L2-resident)
        #pragma unroll
        for (int p = 0; p < 16; ++p) {
            int row = p * 8 + (tid >> 4);
            if (row < cnt) {
                int c4 = tid & 15;
                int cc = (c4 * 4) ^ ((row & 7) << 3);
                float w = meta_w[buf * 128 + row];
                float4 v = *reinterpret_cast<float4*>(&stg[row * 64 + cc]);
                v.x *= w; v.y *= w; v.z *= w; v.w *= w;
                int d = meta_d[buf * 128 + row];
                float* pdst = &out[(size_t)d * DD + c4 * 4];
                asm volatile("red.global.add.v4.f32 [%0], {%1, %2, %3, %4};"
                             :: "l"(pdst), "f"(v.x), "f"(v.y), "f"(v.z), "f"(v.w) : "memory");
            }
        }
    }
}

// ---------------- aux ----------------

__global__ void zero_x1_kernel(int n4)
{
    int i = blockIdx.x * blockDim.x + threadIdx.x;
    if (i < n4) reinterpret_cast<float4*>(g_x1)[i] = make_float4(0.f, 0.f, 0.f, 0.f);
}

__global__ void relu_bias_kernel(float* __restrict__ out,
                                 const float* __restrict__ bias, int n4)
{
    int f = blockIdx.x * blockDim.x + threadIdx.x;
    if (f >= n4) return;
    int c4 = (f & 15) << 2;
    float4 v = reinterpret_cast<float4*>(out)[f];
    v.x = fmaxf(v.x + bias[c4 + 0], 0.f);
    v.y = fmaxf(v.y + bias[c4 + 1], 0.f);
    v.z = fmaxf(v.z + bias[c4 + 2], 0.f);
    v.w = fmaxf(v.w + bias[c4 + 3], 0.f);
    reinterpret_cast<float4*>(out)[f] = v;
}

extern "C" void kernel_launch(void* const* d_in, const int* in_sizes, int n_in,
                              void* d_out, int out_size)
{
    const float* x   = (const float*)d_in[0];
    const int*   ei  = (const int*)  d_in[1];
    const int*   et  = (const int*)  d_in[2];
    const float* pl  = (const float*)d_in[3];
    const float* w1  = (const float*)d_in[4];
    const float* b1  = (const float*)d_in[5];
    const float* w2  = (const float*)d_in[6];
    const float* b2  = (const float*)d_in[7];

    const int N    = in_sizes[0] / DD;
    const int E0   = in_sizes[1] / 2;
    const int nTot = in_sizes[2];

    const int sgrid = (nTot + 1023) / 1024;
    const int n4    = N * (DD / 4);
    const int splitG = (N * 8 + 255) / 256;

    cudaFuncSetAttribute(edge_mma,
                         cudaFuncAttributeMaxDynamicSharedMemorySize, SMEM_BYTES);

    // prep: W conversion (+rcnt zero), counting sort, per-node x split
    convert_W<<<32, 256>>>(w1, w2);
    hist_kernel<<<sgrid, 256>>>(et, nTot);
    scan_tiles<<<1, 512>>>();
    fill_kernel<<<sgrid, 256>>>(ei, et, pl, E0, nTot);
    split_x<false><<<splitG, 256>>>(x, nullptr, N);

    // layer 1: fused transform+scatter into g_x1
    zero_x1_kernel<<<(n4 + 255) / 256, 256>>>(n4);
    edge_mma<<<GRID_MMA, 128, SMEM_BYTES>>>(0, nullptr, 1);

    // layer 2: split relu(x1+b1), then fused transform+scatter into d_out
    split_x<true><<<splitG, 256>>>(nullptr, b1, N);
    cudaMemsetAsync(d_out, 0, (size_t)N * DD * sizeof(float));
    edge_mma<<<GRID_MMA, 128, SMEM_BYTES>>>(1, (float*)d_out, 0);
    relu_bias_kernel<<<(n4 + 255) / 256, 256>>>((float*)d_out, b2, n4);
}